// round 4
// baseline (speedup 1.0000x reference)
#include <cuda_runtime.h>
#include <math.h>

#define B_SZ 8
#define C_SZ 256
#define H_SZ 96
#define W_SZ 96
#define HW   (H_SZ * W_SZ)   // 9216

// ---------------- scratch (static device allocations; no runtime alloc) ----------------
__device__ float g_yu[B_SZ * HW];                       // upsampled y, [B][H][W]
__device__ float g_Aq[C_SZ], g_Bq[C_SZ], g_Ak[C_SZ], g_Bk[C_SZ];
__device__ float g_q[(size_t)B_SZ * H_SZ * C_SZ * W_SZ];  // [B][H][C][W]
__device__ float g_k[(size_t)B_SZ * H_SZ * C_SZ * W_SZ];
__device__ float g_v[(size_t)B_SZ * H_SZ * C_SZ * W_SZ];

// ---------------- kernel 0: fold y-branch weights ----------------
// yq = yu * Aq + Bq  with  Aq = wq@wy,  Bq = wq@by + bq   (same for k)
__global__ void prep_kernel(const float* __restrict__ wy, const float* __restrict__ by,
                            const float* __restrict__ wq, const float* __restrict__ bq,
                            const float* __restrict__ wk, const float* __restrict__ bk)
{
    int c = threadIdx.x;
    const float* wqr = wq + c * C_SZ;
    const float* wkr = wk + c * C_SZ;
    float aq = 0.f, bqs = 0.f, ak = 0.f, bks = 0.f;
    for (int j = 0; j < C_SZ; j++) {
        float wyj = wy[j], byj = by[j];
        aq += wqr[j] * wyj;  bqs += wqr[j] * byj;
        ak += wkr[j] * wyj;  bks += wkr[j] * byj;
    }
    g_Aq[c] = aq;  g_Bq[c] = bqs + bq[c];
    g_Ak[c] = ak;  g_Bk[c] = bks + bk[c];
}

// ---------------- kernel 1: bilinear 24x24 -> 96x96 (half-pixel, edge-clamped) ----------------
__global__ void upsample_kernel(const float* __restrict__ y)
{
    int idx = blockIdx.x * blockDim.x + threadIdx.x;
    if (idx >= B_SZ * HW) return;
    int b  = idx / HW;
    int r  = idx - b * HW;
    int oh = r / W_SZ;
    int ow = r - oh * W_SZ;
    float sy = (oh + 0.5f) * 0.25f - 0.5f;
    float sx = (ow + 0.5f) * 0.25f - 0.5f;
    int y0 = (int)floorf(sy);  float fy = sy - (float)y0;
    int x0 = (int)floorf(sx);  float fx = sx - (float)x0;
    int y0c = max(0, min(23, y0)),     y1c = max(0, min(23, y0 + 1));
    int x0c = max(0, min(23, x0)),     x1c = max(0, min(23, x0 + 1));
    const float* yb = y + b * 576;
    float v00 = yb[y0c * 24 + x0c], v01 = yb[y0c * 24 + x1c];
    float v10 = yb[y1c * 24 + x0c], v11 = yb[y1c * 24 + x1c];
    g_yu[idx] = (1.f - fy) * ((1.f - fx) * v00 + fx * v01)
              +        fy  * ((1.f - fx) * v10 + fx * v11);
}

// ---------------- kernel 2: fused QKV conv as SGEMM + gate + transpose ----------------
// Per batch:  U = Wcat[768,256] @ X[256,9216].  Rows 0-255: q (gated), 256-511: k (gated),
// 512-767: v.  Epilogue writes [B][H][C][W].
__global__ __launch_bounds__(256, 2) void conv_gemm_kernel(
    const float* __restrict__ x,
    const float* __restrict__ wq, const float* __restrict__ bq,
    const float* __restrict__ wk, const float* __restrict__ bk,
    const float* __restrict__ wv, const float* __restrict__ bv)
{
    __shared__ float As[2][16][132];   // A tile transposed (k-major), padded
    __shared__ float Bs[2][16][128];

    int b  = blockIdx.z;
    int n0 = blockIdx.x * 128;
    int m0 = blockIdx.y * 128;
    int sel = m0 >> 8;                          // 0=q, 1=k, 2=v
    const float* W    = (sel == 0) ? wq : (sel == 1) ? wk : wv;
    const float* bias = (sel == 0) ? bq : (sel == 1) ? bk : bv;
    int mrow0 = m0 & 255;
    const float* Xb = x + (size_t)b * C_SZ * HW;

    int tid = threadIdx.x;
    int a_k = (tid & 3) * 4;
    int a_m = tid >> 2;          // 0..63
    int b_n = (tid & 31) * 4;
    int b_k = tid >> 5;          // 0..7
    int tx  = tid & 15, ty = tid >> 4;

    float acc[8][8];
    #pragma unroll
    for (int i = 0; i < 8; i++)
        #pragma unroll
        for (int j = 0; j < 8; j++) acc[i][j] = 0.f;

    auto load_tiles = [&](int k0, int buf) {
        #pragma unroll
        for (int p = 0; p < 2; p++) {
            int m = a_m + p * 64;
            float4 v = *reinterpret_cast<const float4*>(&W[(mrow0 + m) * C_SZ + k0 + a_k]);
            As[buf][a_k + 0][m] = v.x;
            As[buf][a_k + 1][m] = v.y;
            As[buf][a_k + 2][m] = v.z;
            As[buf][a_k + 3][m] = v.w;
        }
        #pragma unroll
        for (int p = 0; p < 2; p++) {
            int kk = b_k + p * 8;
            *reinterpret_cast<float4*>(&Bs[buf][kk][b_n]) =
                *reinterpret_cast<const float4*>(&Xb[(size_t)(k0 + kk) * HW + n0 + b_n]);
        }
    };

    load_tiles(0, 0);
    __syncthreads();

    #pragma unroll 1
    for (int kt = 0; kt < 16; kt++) {
        int buf = kt & 1;
        if (kt < 15) load_tiles((kt + 1) * 16, buf ^ 1);
        #pragma unroll
        for (int kk = 0; kk < 16; kk++) {
            float a[8], bb[8];
            *reinterpret_cast<float4*>(&a[0])  = *reinterpret_cast<const float4*>(&As[buf][kk][ty * 8]);
            *reinterpret_cast<float4*>(&a[4])  = *reinterpret_cast<const float4*>(&As[buf][kk][ty * 8 + 4]);
            *reinterpret_cast<float4*>(&bb[0]) = *reinterpret_cast<const float4*>(&Bs[buf][kk][tx * 8]);
            *reinterpret_cast<float4*>(&bb[4]) = *reinterpret_cast<const float4*>(&Bs[buf][kk][tx * 8 + 4]);
            #pragma unroll
            for (int i = 0; i < 8; i++)
                #pragma unroll
                for (int j = 0; j < 8; j++)
                    acc[i][j] += a[i] * bb[j];
        }
        __syncthreads();
    }

    // epilogue: bias, gate (q/k), write transposed [B][H][C][W]
    float* outbuf = (sel == 0) ? g_q : (sel == 1) ? g_k : g_v;
    const float* Agp = (sel == 0) ? g_Aq : g_Ak;
    const float* Bgp = (sel == 0) ? g_Bq : g_Bk;
    const float* yub = g_yu + b * HW;

    float yuv[8];
    if (sel < 2) {
        #pragma unroll
        for (int j = 0; j < 8; j++) yuv[j] = yub[n0 + tx * 8 + j];
    }

    #pragma unroll
    for (int i = 0; i < 8; i++) {
        int c = mrow0 + ty * 8 + i;
        float bi = bias[c];
        float Ag = 0.f, Bg = 0.f;
        if (sel < 2) { Ag = Agp[c]; Bg = Bgp[c]; }
        #pragma unroll
        for (int j = 0; j < 8; j++) {
            int n = n0 + tx * 8 + j;
            float val = acc[i][j] + bi;
            if (sel < 2) val *= (yuv[j] * Ag + Bg);
            int h = n / 96;
            int w = n - h * 96;
            outbuf[(((size_t)b * H_SZ + h) * C_SZ + c) * W_SZ + w] = val;
        }
    }
}

// ---------------- kernel 3: channel attention, one CTA per (b,h) ----------------
// S = Q K^T / sqrt(32)  (256x256, K=96); softmax rows; O = P V (256x96, K=256).
#define KS_STRIDE 257
#define QS_STRIDE 65
#define PS_STRIDE 65
#define ATTN_SMEM_FLOATS (96 * KS_STRIDE + 96 * QS_STRIDE + 256 * PS_STRIDE)  // 47552
#define ATTN_SMEM_BYTES  (ATTN_SMEM_FLOATS * 4)                               // 190208

__global__ __launch_bounds__(256, 1) void attn_kernel(float* __restrict__ out)
{
    extern __shared__ float sm[];
    float* Ks = sm;                       // [w][d]  96 x 257 (transposed K)
    float* Qs = Ks + 96 * KS_STRIDE;      // [w][r]  96 x 65  (also reused as V chunk [64][96])
    float* Ps = Qs + 96 * QS_STRIDE;      // [d][r] 256 x 65  (transposed P)

    int bh = blockIdx.x;
    int b  = bh / H_SZ;
    int h  = bh - b * H_SZ;
    const float* Q = g_q + (size_t)bh * C_SZ * W_SZ;
    const float* K = g_k + (size_t)bh * C_SZ * W_SZ;
    const float* V = g_v + (size_t)bh * C_SZ * W_SZ;

    int tid = threadIdx.x;
    int ty  = tid >> 5;   // warp 0..7 -> owns 8 S-rows
    int tx  = tid & 31;   // lane      -> owns cols tx + 32*j

    // K -> smem transposed (conflict-free: stride 257)
    for (int idx = tid; idx < C_SZ * W_SZ; idx += 256) {
        int d = idx / W_SZ;
        int w = idx - d * W_SZ;
        Ks[w * KS_STRIDE + d] = K[idx];
    }
    __syncthreads();

    const float inv_s = 0.17677669529663687f;  // 1/sqrt(32)

    for (int t = 0; t < 4; t++) {
        int r0 = t * 64;

        // Q tile -> smem transposed
        for (int idx = tid; idx < 64 * W_SZ; idx += 256) {
            int r = idx / W_SZ;
            int w = idx - r * W_SZ;
            Qs[w * QS_STRIDE + r] = Q[r0 * W_SZ + idx - r * W_SZ + r * W_SZ];  // = Q[(r0+r)*96+w]
        }
        __syncthreads();

        // S = Qt @ K^T, 64x256 in registers (8x8 per thread)
        float acc[8][8];
        #pragma unroll
        for (int i = 0; i < 8; i++)
            #pragma unroll
            for (int j = 0; j < 8; j++) acc[i][j] = 0.f;

        const float* qb = Qs + ty * 8;
        const float* kb = Ks + tx;
        #pragma unroll 2
        for (int w = 0; w < 96; w++) {
            float a[8], bb[8];
            #pragma unroll
            for (int i = 0; i < 8; i++) a[i] = qb[w * QS_STRIDE + i];
            #pragma unroll
            for (int j = 0; j < 8; j++) bb[j] = kb[w * KS_STRIDE + j * 32];
            #pragma unroll
            for (int i = 0; i < 8; i++)
                #pragma unroll
                for (int j = 0; j < 8; j++)
                    acc[i][j] += a[i] * bb[j];
        }

        // softmax per row (row fully inside one warp), then store P transposed
        #pragma unroll
        for (int i = 0; i < 8; i++) {
            float m = acc[i][0];
            #pragma unroll
            for (int j = 1; j < 8; j++) m = fmaxf(m, acc[i][j]);
            #pragma unroll
            for (int off = 16; off > 0; off >>= 1)
                m = fmaxf(m, __shfl_xor_sync(0xffffffffu, m, off));
            float s = 0.f;
            #pragma unroll
            for (int j = 0; j < 8; j++) {
                float p = __expf((acc[i][j] - m) * inv_s);
                acc[i][j] = p;
                s += p;
            }
            #pragma unroll
            for (int off = 16; off > 0; off >>= 1)
                s += __shfl_xor_sync(0xffffffffu, s, off);
            float rs = 1.f / s;
            int r = ty * 8 + i;
            #pragma unroll
            for (int j = 0; j < 8; j++)
                Ps[(tx + j * 32) * PS_STRIDE + r] = acc[i][j] * rs;  // lane-stride 65: conflict-free
        }
        __syncthreads();   // P visible; all Qs reads done (V chunk reuses Qs)

        // O = P @ V, streaming V in 64-row chunks through the Qs buffer
        float acco[8][3];
        #pragma unroll
        for (int i = 0; i < 8; i++)
            #pragma unroll
            for (int j = 0; j < 3; j++) acco[i][j] = 0.f;

        for (int dc = 0; dc < 4; dc++) {
            for (int idx = tid; idx < 64 * W_SZ; idx += 256)
                Qs[idx] = V[dc * 64 * W_SZ + idx];
            __syncthreads();
            const float* pb = Ps + (dc * 64) * PS_STRIDE + ty * 8;
            const float* vb = Qs + tx;
            #pragma unroll 2
            for (int dd = 0; dd < 64; dd++) {
                float a[8], bb[3];
                #pragma unroll
                for (int i = 0; i < 8; i++) a[i] = pb[dd * PS_STRIDE + i];
                #pragma unroll
                for (int j = 0; j < 3; j++) bb[j] = vb[dd * W_SZ + j * 32];
                #pragma unroll
                for (int i = 0; i < 8; i++)
                    #pragma unroll
                    for (int j = 0; j < 3; j++)
                        acco[i][j] += a[i] * bb[j];
            }
            __syncthreads();
        }

        // write O back as [B][C][H][W]
        float* ob = out + (size_t)b * C_SZ * HW + (size_t)h * W_SZ + tx;
        #pragma unroll
        for (int i = 0; i < 8; i++) {
            int c = r0 + ty * 8 + i;
            #pragma unroll
            for (int j = 0; j < 3; j++)
                ob[(size_t)c * HW + j * 32] = acco[i][j];
        }
    }
}

// ---------------- launch ----------------
extern "C" void kernel_launch(void* const* d_in, const int* in_sizes, int n_in,
                              void* d_out, int out_size)
{
    const float* x  = (const float*)d_in[0];
    const float* y  = (const float*)d_in[1];
    const float* wy = (const float*)d_in[2];
    const float* by = (const float*)d_in[3];
    const float* wq = (const float*)d_in[4];
    const float* bq = (const float*)d_in[5];
    const float* wk = (const float*)d_in[6];
    const float* bk = (const float*)d_in[7];
    const float* wv = (const float*)d_in[8];
    const float* bv = (const float*)d_in[9];
    float* out = (float*)d_out;

    cudaFuncSetAttribute(attn_kernel, cudaFuncAttributeMaxDynamicSharedMemorySize,
                         ATTN_SMEM_BYTES);

    prep_kernel<<<1, 256>>>(wy, by, wq, bq, wk, bk);
    upsample_kernel<<<(B_SZ * HW + 255) / 256, 256>>>(y);
    dim3 g(HW / 128, 768 / 128, B_SZ);   // (72, 6, 8)
    conv_gemm_kernel<<<g, 256>>>(x, wq, bq, wk, bk, wv, bv);
    attn_kernel<<<B_SZ * H_SZ, 256, ATTN_SMEM_BYTES>>>(out);
}

// round 5
// speedup vs baseline: 1.0924x; 1.0924x over previous
#include <cuda_runtime.h>
#include <math.h>

#define B_SZ 8
#define C_SZ 256
#define H_SZ 96
#define W_SZ 96
#define HW   (H_SZ * W_SZ)   // 9216

typedef unsigned long long ull;

// ---------------- packed f32x2 helpers (FFMA2 path) ----------------
__device__ __forceinline__ ull pack2(float x, float y) {
    ull r;
    asm("mov.b64 %0, {%1, %2};" : "=l"(r) : "f"(x), "f"(y));
    return r;
}
__device__ __forceinline__ void unpack2(ull v, float& x, float& y) {
    asm("mov.b64 {%0, %1}, %2;" : "=f"(x), "=f"(y) : "l"(v));
}
__device__ __forceinline__ void ffma2(ull& d, ull a, ull b) {
    asm("fma.rn.f32x2 %0, %1, %2, %3;" : "=l"(d) : "l"(a), "l"(b), "l"(d));
}

// ---------------- scratch (static device allocations; no runtime alloc) ----------------
__device__ float g_yu[B_SZ * HW];                       // upsampled y, [B][H][W]
__device__ float g_Aq[C_SZ], g_Bq[C_SZ], g_Ak[C_SZ], g_Bk[C_SZ];
__device__ float g_q[(size_t)B_SZ * H_SZ * C_SZ * W_SZ];  // [B][H][C][W]
__device__ float g_k[(size_t)B_SZ * H_SZ * C_SZ * W_SZ];
__device__ float g_v[(size_t)B_SZ * H_SZ * C_SZ * W_SZ];

// ---------------- kernel 0: fold y-branch weights ----------------
__global__ void prep_kernel(const float* __restrict__ wy, const float* __restrict__ by,
                            const float* __restrict__ wq, const float* __restrict__ bq,
                            const float* __restrict__ wk, const float* __restrict__ bk)
{
    int c = threadIdx.x;
    const float* wqr = wq + c * C_SZ;
    const float* wkr = wk + c * C_SZ;
    float aq = 0.f, bqs = 0.f, ak = 0.f, bks = 0.f;
    for (int j = 0; j < C_SZ; j++) {
        float wyj = wy[j], byj = by[j];
        aq += wqr[j] * wyj;  bqs += wqr[j] * byj;
        ak += wkr[j] * wyj;  bks += wkr[j] * byj;
    }
    g_Aq[c] = aq;  g_Bq[c] = bqs + bq[c];
    g_Ak[c] = ak;  g_Bk[c] = bks + bk[c];
}

// ---------------- kernel 1: bilinear 24x24 -> 96x96 (half-pixel, edge-clamped) ----------------
__global__ void upsample_kernel(const float* __restrict__ y)
{
    int idx = blockIdx.x * blockDim.x + threadIdx.x;
    if (idx >= B_SZ * HW) return;
    int b  = idx / HW;
    int r  = idx - b * HW;
    int oh = r / W_SZ;
    int ow = r - oh * W_SZ;
    float sy = (oh + 0.5f) * 0.25f - 0.5f;
    float sx = (ow + 0.5f) * 0.25f - 0.5f;
    int y0 = (int)floorf(sy);  float fy = sy - (float)y0;
    int x0 = (int)floorf(sx);  float fx = sx - (float)x0;
    int y0c = max(0, min(23, y0)),     y1c = max(0, min(23, y0 + 1));
    int x0c = max(0, min(23, x0)),     x1c = max(0, min(23, x0 + 1));
    const float* yb = y + b * 576;
    float v00 = yb[y0c * 24 + x0c], v01 = yb[y0c * 24 + x1c];
    float v10 = yb[y1c * 24 + x0c], v11 = yb[y1c * 24 + x1c];
    g_yu[idx] = (1.f - fy) * ((1.f - fx) * v00 + fx * v01)
              +        fy  * ((1.f - fx) * v10 + fx * v11);
}

// ---------------- kernel 2: fused QKV conv as SGEMM (FFMA2) + gate + transpose ----------------
__global__ __launch_bounds__(256, 2) void conv_gemm_kernel(
    const float* __restrict__ x,
    const float* __restrict__ wq, const float* __restrict__ bq,
    const float* __restrict__ wk, const float* __restrict__ bk,
    const float* __restrict__ wv, const float* __restrict__ bv)
{
    __shared__ __align__(16) float As[2][16][132];   // A tile transposed (k-major), padded
    __shared__ __align__(16) float Bs[2][16][128];

    int b  = blockIdx.z;
    int n0 = blockIdx.x * 128;
    int m0 = blockIdx.y * 128;
    int sel = m0 >> 8;                          // 0=q, 1=k, 2=v
    const float* W    = (sel == 0) ? wq : (sel == 1) ? wk : wv;
    const float* bias = (sel == 0) ? bq : (sel == 1) ? bk : bv;
    int mrow0 = m0 & 255;
    const float* Xb = x + (size_t)b * C_SZ * HW;

    int tid = threadIdx.x;
    int a_k = (tid & 3) * 4;
    int a_m = tid >> 2;          // 0..63
    int b_n = (tid & 31) * 4;
    int b_k = tid >> 5;          // 0..7
    int tx  = tid & 15, ty = tid >> 4;

    ull acc2[8][4];
    #pragma unroll
    for (int i = 0; i < 8; i++)
        #pragma unroll
        for (int j = 0; j < 4; j++) acc2[i][j] = 0ULL;

    auto load_tiles = [&](int k0, int buf) {
        #pragma unroll
        for (int p = 0; p < 2; p++) {
            int m = a_m + p * 64;
            float4 v = *reinterpret_cast<const float4*>(&W[(mrow0 + m) * C_SZ + k0 + a_k]);
            As[buf][a_k + 0][m] = v.x;
            As[buf][a_k + 1][m] = v.y;
            As[buf][a_k + 2][m] = v.z;
            As[buf][a_k + 3][m] = v.w;
        }
        #pragma unroll
        for (int p = 0; p < 2; p++) {
            int kk = b_k + p * 8;
            *reinterpret_cast<float4*>(&Bs[buf][kk][b_n]) =
                *reinterpret_cast<const float4*>(&Xb[(size_t)(k0 + kk) * HW + n0 + b_n]);
        }
    };

    load_tiles(0, 0);
    __syncthreads();

    #pragma unroll 1
    for (int kt = 0; kt < 16; kt++) {
        int buf = kt & 1;
        if (kt < 15) load_tiles((kt + 1) * 16, buf ^ 1);
        #pragma unroll
        for (int kk = 0; kk < 16; kk++) {
            // b pairs (n-contiguous) come straight out of two LDS.128
            longlong2 bl0 = *reinterpret_cast<const longlong2*>(&Bs[buf][kk][tx * 8]);
            longlong2 bl1 = *reinterpret_cast<const longlong2*>(&Bs[buf][kk][tx * 8 + 4]);
            ull bp[4];
            bp[0] = (ull)bl0.x; bp[1] = (ull)bl0.y;
            bp[2] = (ull)bl1.x; bp[3] = (ull)bl1.y;
            float4 a0 = *reinterpret_cast<const float4*>(&As[buf][kk][ty * 8]);
            float4 a1 = *reinterpret_cast<const float4*>(&As[buf][kk][ty * 8 + 4]);
            float av[8] = {a0.x, a0.y, a0.z, a0.w, a1.x, a1.y, a1.z, a1.w};
            #pragma unroll
            for (int i = 0; i < 8; i++) {
                ull aa = pack2(av[i], av[i]);
                #pragma unroll
                for (int j = 0; j < 4; j++)
                    ffma2(acc2[i][j], aa, bp[j]);
            }
        }
        __syncthreads();
    }

    // epilogue: bias, gate (q/k), write transposed [B][H][C][W]
    float* outbuf = (sel == 0) ? g_q : (sel == 1) ? g_k : g_v;
    const float* Agp = (sel == 0) ? g_Aq : g_Ak;
    const float* Bgp = (sel == 0) ? g_Bq : g_Bk;
    const float* yub = g_yu + b * HW;

    float yuv[8];
    if (sel < 2) {
        #pragma unroll
        for (int j = 0; j < 8; j++) yuv[j] = yub[n0 + tx * 8 + j];
    }

    #pragma unroll
    for (int i = 0; i < 8; i++) {
        int c = mrow0 + ty * 8 + i;
        float bi = bias[c];
        float Ag = 0.f, Bg = 0.f;
        if (sel < 2) { Ag = Agp[c]; Bg = Bgp[c]; }
        float row[8];
        #pragma unroll
        for (int j = 0; j < 4; j++) unpack2(acc2[i][j], row[2 * j], row[2 * j + 1]);
        #pragma unroll
        for (int j = 0; j < 8; j++) {
            int n = n0 + tx * 8 + j;
            float val = row[j] + bi;
            if (sel < 2) val *= (yuv[j] * Ag + Bg);
            int h = n / 96;
            int w = n - h * 96;
            outbuf[(((size_t)b * H_SZ + h) * C_SZ + c) * W_SZ + w] = val;
        }
    }
}

// ---------------- kernel 3: channel attention (FFMA2), one CTA per (b,h) ----------------
// S = Q K^T / sqrt(32)  (256x256, K=96); softmax rows; O = P V (256x96, K=256).
#define KS_STRIDE 258   // even -> conflict-free LDS.64 column-pair reads
#define QS_STRIDE 65
#define PS_STRIDE 66    // even -> broadcast LDS.64 row-pair reads in PV
#define ATTN_SMEM_FLOATS (96 * KS_STRIDE + 96 * QS_STRIDE + 256 * PS_STRIDE)  // 47904
#define ATTN_SMEM_BYTES  (ATTN_SMEM_FLOATS * 4)                               // 191616

__global__ __launch_bounds__(256, 1) void attn_kernel(float* __restrict__ out)
{
    extern __shared__ __align__(16) float sm[];
    float* Ks = sm;                       // [w][d]  96 x 258 (transposed K)
    float* Qs = Ks + 96 * KS_STRIDE;      // [w][r]  96 x 65  (also reused as V chunk [64][96])
    float* Ps = Qs + 96 * QS_STRIDE;      // [d][r] 256 x 66  (transposed P)

    int bh = blockIdx.x;
    int b  = bh / H_SZ;
    int h  = bh - b * H_SZ;
    const float* Q = g_q + (size_t)bh * C_SZ * W_SZ;
    const float* K = g_k + (size_t)bh * C_SZ * W_SZ;
    const float* V = g_v + (size_t)bh * C_SZ * W_SZ;

    int tid = threadIdx.x;
    int ty  = tid >> 5;   // warp 0..7 -> owns 8 S-rows
    int tx  = tid & 31;   // lane      -> owns col pairs {2*tx+64j, 2*tx+1+64j}

    // K -> smem transposed
    for (int idx = tid; idx < C_SZ * W_SZ; idx += 256) {
        int d = idx / W_SZ;
        int w = idx - d * W_SZ;
        Ks[w * KS_STRIDE + d] = K[idx];
    }
    __syncthreads();

    const float inv_s = 0.17677669529663687f;  // 1/sqrt(32)

    for (int t = 0; t < 4; t++) {
        int r0 = t * 64;

        // Q tile -> smem transposed
        for (int idx = tid; idx < 64 * W_SZ; idx += 256) {
            int r = idx / W_SZ;
            int w = idx - r * W_SZ;
            Qs[w * QS_STRIDE + r] = Q[(r0 + r) * W_SZ + w];
        }
        __syncthreads();

        // S = Qt @ K^T, 64x256; 8 rows x 4 col-pairs per thread (FFMA2)
        ull acc2[8][4];
        #pragma unroll
        for (int i = 0; i < 8; i++)
            #pragma unroll
            for (int j = 0; j < 4; j++) acc2[i][j] = 0ULL;

        const float* qb = Qs + ty * 8;
        const float* kb = Ks + 2 * tx;
        #pragma unroll 2
        for (int w = 0; w < 96; w++) {
            ull bp[4];
            #pragma unroll
            for (int j = 0; j < 4; j++)
                bp[j] = *reinterpret_cast<const ull*>(&kb[w * KS_STRIDE + j * 64]);
            #pragma unroll
            for (int i = 0; i < 8; i++) {
                float a = qb[w * QS_STRIDE + i];
                ull aa = pack2(a, a);
                #pragma unroll
                for (int j = 0; j < 4; j++)
                    ffma2(acc2[i][j], aa, bp[j]);
            }
        }

        // softmax per row (row fully inside one warp), store P transposed
        #pragma unroll
        for (int i = 0; i < 8; i++) {
            float p[8];
            #pragma unroll
            for (int j = 0; j < 4; j++) unpack2(acc2[i][j], p[2 * j], p[2 * j + 1]);
            float m = p[0];
            #pragma unroll
            for (int j = 1; j < 8; j++) m = fmaxf(m, p[j]);
            #pragma unroll
            for (int off = 16; off > 0; off >>= 1)
                m = fmaxf(m, __shfl_xor_sync(0xffffffffu, m, off));
            float s = 0.f;
            #pragma unroll
            for (int j = 0; j < 8; j++) {
                float e = __expf((p[j] - m) * inv_s);
                p[j] = e;
                s += e;
            }
            #pragma unroll
            for (int off = 16; off > 0; off >>= 1)
                s += __shfl_xor_sync(0xffffffffu, s, off);
            float rs = 1.f / s;
            int r = ty * 8 + i;
            #pragma unroll
            for (int j = 0; j < 4; j++) {
                Ps[(2 * tx + 64 * j    ) * PS_STRIDE + r] = p[2 * j]     * rs;
                Ps[(2 * tx + 64 * j + 1) * PS_STRIDE + r] = p[2 * j + 1] * rs;
            }
        }
        __syncthreads();   // P visible; all Qs reads done (V chunk reuses Qs)

        // O = P @ V; 4 row-pairs x 3 cols per thread (FFMA2)
        ull acco2[4][3];
        #pragma unroll
        for (int i = 0; i < 4; i++)
            #pragma unroll
            for (int j = 0; j < 3; j++) acco2[i][j] = 0ULL;

        for (int dc = 0; dc < 4; dc++) {
            for (int idx = tid; idx < 64 * W_SZ; idx += 256)
                Qs[idx] = V[dc * 64 * W_SZ + idx];
            __syncthreads();
            const float* pb = Ps + (dc * 64) * PS_STRIDE + ty * 8;
            const float* vb = Qs + tx;
            #pragma unroll 2
            for (int dd = 0; dd < 64; dd++) {
                ull ap[4];
                #pragma unroll
                for (int ii = 0; ii < 4; ii++)
                    ap[ii] = *reinterpret_cast<const ull*>(&pb[dd * PS_STRIDE + 2 * ii]);
                #pragma unroll
                for (int j = 0; j < 3; j++) {
                    float bv = vb[dd * W_SZ + j * 32];
                    ull bp = pack2(bv, bv);
                    #pragma unroll
                    for (int ii = 0; ii < 4; ii++)
                        ffma2(acco2[ii][j], ap[ii], bp);
                }
            }
            __syncthreads();
        }

        // write O back as [B][C][H][W]
        float* ob = out + (size_t)b * C_SZ * HW + (size_t)h * W_SZ + tx;
        #pragma unroll
        for (int ii = 0; ii < 4; ii++) {
            int c = r0 + ty * 8 + 2 * ii;
            #pragma unroll
            for (int j = 0; j < 3; j++) {
                float o0, o1;
                unpack2(acco2[ii][j], o0, o1);
                ob[(size_t)c       * HW + j * 32] = o0;
                ob[(size_t)(c + 1) * HW + j * 32] = o1;
            }
        }
    }
}

// ---------------- launch ----------------
extern "C" void kernel_launch(void* const* d_in, const int* in_sizes, int n_in,
                              void* d_out, int out_size)
{
    const float* x  = (const float*)d_in[0];
    const float* y  = (const float*)d_in[1];
    const float* wy = (const float*)d_in[2];
    const float* by = (const float*)d_in[3];
    const float* wq = (const float*)d_in[4];
    const float* bq = (const float*)d_in[5];
    const float* wk = (const float*)d_in[6];
    const float* bk = (const float*)d_in[7];
    const float* wv = (const float*)d_in[8];
    const float* bv = (const float*)d_in[9];
    float* out = (float*)d_out;

    cudaFuncSetAttribute(attn_kernel, cudaFuncAttributeMaxDynamicSharedMemorySize,
                         ATTN_SMEM_BYTES);

    prep_kernel<<<1, 256>>>(wy, by, wq, bq, wk, bk);
    upsample_kernel<<<(B_SZ * HW + 255) / 256, 256>>>(y);
    dim3 g(HW / 128, 768 / 128, B_SZ);   // (72, 6, 8)
    conv_gemm_kernel<<<g, 256>>>(x, wq, bq, wk, bk, wv, bv);
    attn_kernel<<<B_SZ * H_SZ, 256, ATTN_SMEM_BYTES>>>(out);
}